// round 5
// baseline (speedup 1.0000x reference)
#include <cuda_runtime.h>
#include <cstdint>

#define D_MODEL 2048
#define BATCH   16384
#define MT 256
#define NT 64
#define A_STAGE 32768
#define B_STAGE 13312
#define STAGE_BYTES 46080        // A 32KB + B 13KB
#define SM_DEC (3*STAGE_BYTES)   // 138240
#define SMEM_TOTAL (SM_DEC + 2048)

// scratch: x in A-fragment order, weights in B-fragment order
__device__ float g_xA[33554432];   // [rt 0..1023][t 0..255][128 w]
__device__ float g_WB[6815744];    // [cb 0..31][bt 0..12][t 0..255][64 w]

__device__ __forceinline__ float tf32r(float x) {
    float y; asm("cvt.rna.tf32.f32 %0, %1;" : "=f"(y) : "f"(x)); return y;
}
__device__ __forceinline__ uint32_t smem_u32(const void* p) {
    uint32_t a;
    asm("{ .reg .u64 t; cvta.to.shared.u64 t, %1; cvt.u32.u64 %0, t; }" : "=r"(a) : "l"(p));
    return a;
}
__device__ __forceinline__ void cp16(uint32_t dst, const void* src) {
    asm volatile("cp.async.cg.shared.global [%0], [%1], 16;" :: "r"(dst), "l"(src));
}
__device__ __forceinline__ void lds128(uint32_t* r, uint32_t a) {
    asm volatile("ld.shared.v4.b32 {%0,%1,%2,%3}, [%4];"
                 : "=r"(r[0]), "=r"(r[1]), "=r"(r[2]), "=r"(r[3]) : "r"(a));
}
__device__ __forceinline__ void lds64(uint32_t* r, uint32_t a) {
    asm volatile("ld.shared.v2.b32 {%0,%1}, [%2];" : "=r"(r[0]), "=r"(r[1]) : "r"(a));
}
__device__ __forceinline__ void mma_tf32(float* c, const uint32_t* a, const uint32_t* b) {
    asm volatile(
        "mma.sync.aligned.m16n8k8.row.col.f32.tf32.tf32.f32 "
        "{%0,%1,%2,%3}, {%4,%5,%6,%7}, {%8,%9}, {%0,%1,%2,%3};\n"
        : "+f"(c[0]), "+f"(c[1]), "+f"(c[2]), "+f"(c[3])
        : "r"(a[0]), "r"(a[1]), "r"(a[2]), "r"(a[3]), "r"(b[0]), "r"(b[1]));
}

// ---- preround x: coalesced LDG -> smem permute -> coalesced STG ----
// block handles rt (16 rows) x 512 cols (t-block of 64). grid = 1024*4.
__global__ __launch_bounds__(256) void preround_x(const float* __restrict__ x) {
    __shared__ float sm[16 * 516];
    const int tid = threadIdx.x;
    const int rt = blockIdx.x >> 2, tb = blockIdx.x & 3;
    const float* src = x + (size_t)rt * 16 * D_MODEL + tb * 512;
    #pragma unroll
    for (int i = 0; i < 8; i++) {
        int f4 = tid + i * 256;
        int row = f4 >> 7, c4 = f4 & 127;
        float4 v = *(const float4*)(src + (size_t)row * D_MODEL + c4 * 4);
        v.x = tf32r(v.x); v.y = tf32r(v.y); v.z = tf32r(v.z); v.w = tf32r(v.w);
        *(float4*)&sm[row * 516 + c4 * 4] = v;
    }
    __syncthreads();
    char* dst = (char*)g_xA + (size_t)rt * 131072 + (size_t)tb * 64 * 512;
    #pragma unroll
    for (int i = 0; i < 8; i++) {
        int f4 = tid + i * 256;
        int tl = f4 >> 5, lane = f4 & 31;
        int g = lane >> 2, tg = lane & 3;
        float4 v;
        v.x = sm[ g      * 516 + tl * 8 + tg    ];   // j=0
        v.y = sm[(g + 8) * 516 + tl * 8 + tg    ];   // j=1
        v.z = sm[ g      * 516 + tl * 8 + tg + 4];   // j=2
        v.w = sm[(g + 8) * 516 + tl * 8 + tg + 4];   // j=3
        *(float4*)(dst + (size_t)tl * 512 + lane * 16) = v;
    }
}

// ---- preround W: W_in/W_angle/W_decay -> concatenated B-fragment order ----
__global__ void preround_w(const float* __restrict__ Wi, const float* __restrict__ Wa,
                           const float* __restrict__ Wd) {
    size_t f = (size_t)blockIdx.x * 256 + threadIdx.x;      // 6815744 total
    int cb = (int)(f / 212992); int rem = (int)(f % 212992);
    int bt = rem >> 14; int rem2 = rem & 16383;
    int t = rem2 >> 6; int w = rem2 & 63;
    int lane = w >> 1, j = w & 1, g = lane >> 2, tg = lane & 3;
    int k = t * 8 + tg + 4 * j;
    float v;
    if (bt < 8)       v = Wi[(size_t)(cb * 64 + bt * 8 + g) * D_MODEL + k];
    else if (bt < 12) v = Wa[(size_t)(cb * 32 + (bt - 8) * 8 + g) * D_MODEL + k];
    else              v = (g == 0) ? Wd[k] : 0.f;
    g_WB[f] = tf32r(v);
}

// ---- main fused kernel: 256 threads, 8 warps (4x2), MT=256, 3-stage ----
__global__ void __launch_bounds__(256, 1) givens_main(
    const float* __restrict__ h_prev, const float* __restrict__ b_angle,
    const float* __restrict__ b_decay, const float* __restrict__ b_in,
    float* __restrict__ out)
{
    extern __shared__ __align__(1024) char smem[];
    const uint32_t sb = smem_u32(smem);
    const int tid = threadIdx.x, warp = tid >> 5, lane = tid & 31;
    const int g = lane >> 2, tg = lane & 3;
    const int wm = warp >> 1, wn = warp & 1;            // 4x2 warp grid
    const int by = blockIdx.y, cb = blockIdx.x;
    const int m0 = by * MT, n0 = cb * NT, a0 = n0 >> 1;

    // per-thread cp.async sources: A 8 float4, B 4 float4 (one predicated)
    const char* xA = (const char*)g_xA + (size_t)by * 2097152;   // 16 rt * 131072 B
    const char* WB = (const char*)g_WB + (size_t)cb * 851968;    // 212992 floats * 4 B
    const char* asrc[8]; uint32_t adst[8];
    #pragma unroll
    for (int it = 0; it < 8; it++) {
        int f4 = it * 256 + tid;
        int lrt = f4 >> 7, inner = f4 & 127;
        asrc[it] = xA + (size_t)lrt * 131072 + inner * 16;
        adst[it] = (uint32_t)(lrt * 2048 + inner * 16);
    }
    const char* bsrc[4]; uint32_t bdst[4];
    #pragma unroll
    for (int ib = 0; ib < 4; ib++) {
        int f4 = ib * 256 + tid;
        int bt = f4 >> 6, inner = f4 & 63;
        bsrc[ib] = WB + (size_t)bt * 65536 + inner * 16;         // 16384 floats * 4 B
        bdst[ib] = (uint32_t)(A_STAGE + bt * 1024 + inner * 16);
    }
    const bool btail = (tid < 64);

    float ci[4][4][4] = {};   // mi, nb, frag
    float ca[4][2][4] = {};   // mi, na, frag
    float cd[4][4]    = {};   // mi, frag (wn==0 only)

    #define ISSUE(CHUNK, STG) do {                                              \
        uint32_t sd = sb + (STG) * STAGE_BYTES;                                 \
        _Pragma("unroll")                                                       \
        for (int it = 0; it < 8; it++)                                          \
            cp16(sd + adst[it], asrc[it] + (size_t)(CHUNK) * 2048);             \
        _Pragma("unroll")                                                       \
        for (int ib = 0; ib < 4; ib++)                                          \
            if (ib < 3 || btail)                                                \
                cp16(sd + bdst[ib], bsrc[ib] + (size_t)(CHUNK) * 1024);         \
        asm volatile("cp.async.commit_group;" ::: "memory");                    \
    } while (0)

    ISSUE(0, 0);
    ISSUE(1, 1);

    #pragma unroll 1
    for (int c = 0; c < 64; c++) {
        asm volatile("cp.async.wait_group 1;" ::: "memory");
        __syncthreads();
        if (c + 2 < 64) { ISSUE(c + 2, (c + 2) % 3); }
        else            { asm volatile("cp.async.commit_group;" ::: "memory"); }

        const uint32_t sa = sb + (c % 3) * STAGE_BYTES;
        #pragma unroll
        for (int kt = 0; kt < 4; kt++) {
            uint32_t a[4][4];
            #pragma unroll
            for (int mi = 0; mi < 4; mi++)
                lds128(a[mi], sa + (uint32_t)(((wm * 4 + mi) * 4 + kt) * 512) + lane * 16);
            #pragma unroll
            for (int nb = 0; nb < 4; nb++) {
                uint32_t b[2];
                lds64(b, sa + A_STAGE + (uint32_t)(((wn * 4 + nb) * 4 + kt) * 256) + lane * 8);
                #pragma unroll
                for (int mi = 0; mi < 4; mi++) mma_tf32(ci[mi][nb], a[mi], b);
            }
            #pragma unroll
            for (int na = 0; na < 2; na++) {
                uint32_t b[2];
                lds64(b, sa + A_STAGE + (uint32_t)(((8 + wn * 2 + na) * 4 + kt) * 256) + lane * 8);
                #pragma unroll
                for (int mi = 0; mi < 4; mi++) mma_tf32(ca[mi][na], a[mi], b);
            }
            if (wn == 0) {
                uint32_t b[2];
                lds64(b, sa + A_STAGE + (uint32_t)((12 * 4 + kt) * 256) + lane * 8);
                #pragma unroll
                for (int mi = 0; mi < 4; mi++) mma_tf32(cd[mi], a[mi], b);
            }
        }
    }
    __syncthreads();

    // ---- epilogue ----
    float* ang_sm = (float*)smem;                       // 256 x 33 (stage0 reuse)
    float* dec_sm = (float*)(smem + SM_DEC);            // 256 floats
    const float bdec = b_decay[0];
    if (wn == 0 && tg == 0) {
        #pragma unroll
        for (int mi = 0; mi < 4; mi++) {
            int r = wm * 64 + mi * 16 + g;
            dec_sm[r]     = 1.f / (1.f + __expf(-(cd[mi][0] + bdec)));
            dec_sm[r + 8] = 1.f / (1.f + __expf(-(cd[mi][2] + bdec)));
        }
    }
    #pragma unroll
    for (int mi = 0; mi < 4; mi++)
    #pragma unroll
    for (int na = 0; na < 2; na++) {
        int rm  = wm * 64 + mi * 16 + g;
        int cbp = wn * 16 + na * 8 + 2 * tg;
        float bA0 = b_angle[a0 + cbp], bA1 = b_angle[a0 + cbp + 1];
        ang_sm[ rm      * 33 + cbp    ] = ca[mi][na][0] + bA0;
        ang_sm[ rm      * 33 + cbp + 1] = ca[mi][na][1] + bA1;
        ang_sm[(rm + 8) * 33 + cbp    ] = ca[mi][na][2] + bA0;
        ang_sm[(rm + 8) * 33 + cbp + 1] = ca[mi][na][3] + bA1;
    }
    __syncthreads();

    #pragma unroll
    for (int mi = 0; mi < 4; mi++)
    #pragma unroll
    for (int nb = 0; nb < 4; nb++) {
        int cloc = wn * 32 + nb * 8 + 2 * tg;
        float2 bi2 = *(const float2*)&b_in[n0 + cloc];
        #pragma unroll
        for (int h = 0; h < 2; h++) {
            int rloc = wm * 64 + mi * 16 + g + h * 8;
            size_t goff = (size_t)(m0 + rloc) * D_MODEL + n0 + cloc;
            float theta = ang_sm[rloc * 33 + (cloc >> 1)];
            float sn, cs;
            __sincosf(theta, &sn, &cs);
            float2 hp = *(const float2*)&h_prev[goff];
            float d = dec_sm[rloc];
            float2 o;
            o.x = d * (cs * hp.x - sn * hp.y) + ci[mi][nb][h * 2 + 0] + bi2.x;
            o.y = d * (sn * hp.x + cs * hp.y) + ci[mi][nb][h * 2 + 1] + bi2.y;
            *(float2*)&out[goff] = o;
        }
    }
    #undef ISSUE
}

extern "C" void kernel_launch(void* const* d_in, const int* in_sizes, int n_in,
                              void* d_out, int out_size) {
    const float* x       = (const float*)d_in[0];
    const float* h_prev  = (const float*)d_in[1];
    const float* W_angle = (const float*)d_in[2];
    const float* b_angle = (const float*)d_in[3];
    const float* W_decay = (const float*)d_in[4];
    const float* b_decay = (const float*)d_in[5];
    const float* W_in    = (const float*)d_in[6];
    const float* b_in    = (const float*)d_in[7];

    preround_x<<<4096, 256>>>(x);
    preround_w<<<26624, 256>>>(W_in, W_angle, W_decay);

    cudaFuncSetAttribute(givens_main, cudaFuncAttributeMaxDynamicSharedMemorySize, SMEM_TOTAL);
    dim3 grid(D_MODEL / NT, BATCH / MT);
    givens_main<<<grid, 256, SMEM_TOTAL>>>(h_prev, b_angle, b_decay, b_in, (float*)d_out);
}